// round 5
// baseline (speedup 1.0000x reference)
#include <cuda_runtime.h>
#include <stdint.h>

// JAX threefry: 1 = jax_threefry_partitionable (modern default; round-4 evidence
// says this is the right scheme — legacy made error worse).
#ifndef PARTITIONABLE
#define PARTITIONABLE 1
#endif

#define BSZ   1024   // batch
#define NDIM  1024   // ecnum == ca1num == ca3num
#define TLEN  100

// d_out layout (float elements), tuple order:
// act_cell(1024*2), ec3his(100*1024), ec5his, ca1his, ec3(1024^2), ec5, ca1
#define OFF_ACT 0
#define OFF_E3H 2048
#define OFF_E5H (2048 + 102400)
#define OFF_C1H (2048 + 2*102400)
#define OFF_EC3 (2048 + 3*102400)
#define OFF_EC5 (OFF_EC3 + 1048576)
#define OFF_CA1 (OFF_EC5 + 1048576)

__device__ float    g_drive[TLEN * NDIM];   // drive_all, precomputed
__device__ uint32_t g_keys[2 * TLEN];       // per-step threefry keys

// TF32 input rounding (round-to-nearest), matching cuBLAS/XLA TF32 GEMM inputs.
__device__ __forceinline__ float tf32r(float x) {
    uint32_t u = __float_as_uint(x);
    asm("cvt.rna.tf32.f32 %0, %0;" : "+r"(u));
    return __uint_as_float(u);
}

// ---------------------------------------------------------------------------
// Threefry-2x32 block cipher, exactly as in jax/_src/prng.py
// ---------------------------------------------------------------------------
__device__ __forceinline__ void threefry2x32(uint32_t k0, uint32_t k1,
                                             uint32_t x0, uint32_t x1,
                                             uint32_t& o0, uint32_t& o1) {
    uint32_t ks2 = k0 ^ k1 ^ 0x1BD11BDAu;
    x0 += k0; x1 += k1;
#define TF_R(r) { x0 += x1; x1 = __funnelshift_l(x1, x1, (r)); x1 ^= x0; }
    TF_R(13) TF_R(15) TF_R(26) TF_R(6)
    x0 += k1;  x1 += ks2 + 1u;
    TF_R(17) TF_R(29) TF_R(16) TF_R(24)
    x0 += ks2; x1 += k0 + 2u;
    TF_R(13) TF_R(15) TF_R(26) TF_R(6)
    x0 += k0;  x1 += k1 + 3u;
    TF_R(17) TF_R(29) TF_R(16) TF_R(24)
    x0 += k1;  x1 += ks2 + 4u;
    TF_R(13) TF_R(15) TF_R(26) TF_R(6)
    x0 += ks2; x1 += k0 + 5u;
#undef TF_R
    o0 = x0; o1 = x1;
}

// split(key(42), 100) -> 100 subkeys; key(42) = (0, 42)
__global__ void keys_kernel() {
    int t = threadIdx.x;
    if (t < TLEN) {
        uint32_t o0, o1;
#if PARTITIONABLE
        // fold-like split: key_t = block((0,42), (hi=0, lo=t))
        threefry2x32(0u, 42u, 0u, (uint32_t)t, o0, o1);
        g_keys[2 * t]     = o0;
        g_keys[2 * t + 1] = o1;
#else
        threefry2x32(0u, 42u, (uint32_t)t, (uint32_t)(TLEN + t), o0, o1);
        g_keys[t]        = o0;
        g_keys[TLEN + t] = o1;
#endif
    }
}

// uniform(key, idx) < 0.004 test for flat index idx in a (1024,1024) draw
__device__ __forceinline__ bool noise_hit(uint32_t k0, uint32_t k1, uint32_t idx) {
    uint32_t o0, o1, bits;
#if PARTITIONABLE
    threefry2x32(k0, k1, 0u, idx, o0, o1);
    bits = o0 ^ o1;
#else
    const uint32_t half = (BSZ * NDIM) / 2;  // 524288
    uint32_t i = idx & (half - 1u);
    threefry2x32(k0, k1, i, half + i, o0, o1);
    bits = (idx < half) ? o0 : o1;
#endif
    float u = __uint_as_float((bits >> 9) | 0x3f800000u) - 1.0f;
    return u < 0.004f;   // NOISE_P = 0.04 * 0.1
}

// ---------------------------------------------------------------------------
// drive_all[t] = exp(-(centers - t)^2 / 50) @ wca3ca1     (one block per t)
// ---------------------------------------------------------------------------
__global__ __launch_bounds__(256) void drive_kernel(const float* __restrict__ wca3ca1) {
    __shared__ float ca3[NDIM];
    const int t = blockIdx.x;
    const float x = (float)t;
    for (int c = threadIdx.x; c < NDIM; c += 256) {
        float center = (100.0f / 1023.0f) * (float)c;   // linspace(0,100,1024)
        float d = center - x;
        ca3[c] = tf32r(expf(-(d * d) / 50.0f));         // 2*SIGMA^2 = 50
    }
    __syncthreads();
    for (int n = threadIdx.x; n < NDIM; n += 256) {
        float acc = 0.0f;
        for (int k = 0; k < NDIM; k++)
            acc += ca3[k] * tf32r(wca3ca1[k * NDIM + n]);
        g_drive[t * NDIM + n] = acc;
    }
}

// ---------------------------------------------------------------------------
// 64x64x16 SGEMM core with TF32-rounded operands (fp32 accumulate):
// C(64x64) tile of A(1024x1024) @ B(1024x1024), 256 threads, 4x4/thread.
// ---------------------------------------------------------------------------
__device__ __forceinline__ void sgemm64(const float* __restrict__ A,
                                        const float* __restrict__ Bw,
                                        float acc[16]) {
    __shared__ float As[16][64];
    __shared__ float Bs[16][64];
    const int tid = threadIdx.x;
    const int tx = tid & 15, ty = tid >> 4;
    const int m0 = blockIdx.y * 64;
    const int n0 = blockIdx.x * 64;

#pragma unroll
    for (int i = 0; i < 16; i++) acc[i] = 0.0f;

    const int arow  = tid >> 2;        // 0..63
    const int acol4 = (tid & 3) * 4;   // 0,4,8,12
    const int brow  = tid >> 4;        // 0..15
    const int bcol4 = (tid & 15) * 4;  // 0..60

    for (int k0 = 0; k0 < NDIM; k0 += 16) {
        float4 av = *(const float4*)&A[(m0 + arow) * NDIM + k0 + acol4];
        float4 bv = *(const float4*)&Bw[(k0 + brow) * NDIM + n0 + bcol4];
        As[acol4 + 0][arow] = tf32r(av.x);
        As[acol4 + 1][arow] = tf32r(av.y);
        As[acol4 + 2][arow] = tf32r(av.z);
        As[acol4 + 3][arow] = tf32r(av.w);
        bv.x = tf32r(bv.x); bv.y = tf32r(bv.y); bv.z = tf32r(bv.z); bv.w = tf32r(bv.w);
        *(float4*)&Bs[brow][bcol4] = bv;
        __syncthreads();
#pragma unroll
        for (int k = 0; k < 16; k++) {
            float4 a = *(const float4*)&As[k][ty * 4];
            float4 b = *(const float4*)&Bs[k][tx * 4];
            acc[0]  += a.x * b.x; acc[1]  += a.x * b.y; acc[2]  += a.x * b.z; acc[3]  += a.x * b.w;
            acc[4]  += a.y * b.x; acc[5]  += a.y * b.y; acc[6]  += a.y * b.z; acc[7]  += a.y * b.w;
            acc[8]  += a.z * b.x; acc[9]  += a.z * b.y; acc[10] += a.z * b.z; acc[11] += a.z * b.w;
            acc[12] += a.w * b.x; acc[13] += a.w * b.y; acc[14] += a.w * b.z; acc[15] += a.w * b.w;
        }
        __syncthreads();
    }
}

__device__ __forceinline__ float sigmoidf(float x) {
    return 1.0f / (1.0f + expf(-x));
}

// step part 1: ca1 = relu(drive_t * (1 + sigmoid(ec3 @ wec3ca1)) - ca1bias)
__global__ __launch_bounds__(256) void step1_kernel(
    const float* __restrict__ ec3, const float* __restrict__ wec3ca1,
    const float* __restrict__ ca1bias, float* __restrict__ ca1,
    float* __restrict__ ca1his, int t)
{
    float acc[16];
    sgemm64(ec3, wec3ca1, acc);
    const int tx = threadIdx.x & 15, ty = threadIdx.x >> 4;
    const int mb = blockIdx.y * 64 + ty * 4;
    const int nb = blockIdx.x * 64 + tx * 4;
    const float* drive = &g_drive[t * NDIM];
#pragma unroll
    for (int i = 0; i < 4; i++) {
        const int b = mb + i;
#pragma unroll
        for (int j = 0; j < 4; j++) {
            const int n = nb + j;
            float v = drive[n] * (1.0f + sigmoidf(acc[i * 4 + j])) - ca1bias[n];
            v = fmaxf(v, 0.0f);
            ca1[b * NDIM + n] = v;
            if (b == 0) ca1his[t * NDIM + n] = v;
        }
    }
}

// step part 2: ec5 += ca1 @ wca1ec5; squash; ec3 *= ec5; cue @ t==10; noise
// cue is read as int32 (the harness converts bool inputs to int32).
__global__ __launch_bounds__(256) void step2_kernel(
    const float* __restrict__ ca1, const float* __restrict__ wca1ec5,
    const int* __restrict__ cue,
    float* __restrict__ ec3, float* __restrict__ ec5,
    float* __restrict__ e3h, float* __restrict__ e5h, int t)
{
    float acc[16];
    sgemm64(ca1, wca1ec5, acc);
    const int tx = threadIdx.x & 15, ty = threadIdx.x >> 4;
    const int mb = blockIdx.y * 64 + ty * 4;
    const int nb = blockIdx.x * 64 + tx * 4;
    const uint32_t k0 = g_keys[2 * t], k1 = g_keys[2 * t + 1];
    const bool at_cue = (t == 10);
#pragma unroll
    for (int i = 0; i < 4; i++) {
        const int b = mb + i;
#pragma unroll
        for (int j = 0; j < 4; j++) {
            const int n = nb + j;
            const int idx = b * NDIM + n;
            float e5 = ec5[idx] + acc[i * 4 + j];          // 10*TS == 1.0 exactly
            e5 = 0.69f + 0.3f * sigmoidf(4.0f * (e5 - 0.3f));
            float e3 = e5 * ec3[idx];
            if (at_cue && (cue[idx] != 0)) e3 = 0.4f * e3 + 0.6f;
            if (noise_hit(k0, k1, (uint32_t)idx)) e3 = 0.5f * e3 + 0.3f;
            ec5[idx] = e5;
            ec3[idx] = e3;
            if (b == 0) { e5h[t * NDIM + n] = e5; e3h[t * NDIM + n] = e3; }
        }
    }
}

// act_cell = ca1 @ wca1act + actbias   (1024x1024 @ 1024x2), TF32 operands
__global__ __launch_bounds__(128) void act_kernel(
    const float* __restrict__ ca1, const float* __restrict__ w,
    const float* __restrict__ bias, float* __restrict__ out)
{
    __shared__ float s0[128], s1[128];
    const int b = blockIdx.x;
    float a0 = 0.0f, a1 = 0.0f;
    for (int c = threadIdx.x; c < NDIM; c += 128) {
        float v = tf32r(ca1[b * NDIM + c]);
        a0 += v * tf32r(w[c * 2 + 0]);
        a1 += v * tf32r(w[c * 2 + 1]);
    }
    s0[threadIdx.x] = a0; s1[threadIdx.x] = a1;
    __syncthreads();
    for (int off = 64; off > 0; off >>= 1) {
        if (threadIdx.x < off) {
            s0[threadIdx.x] += s0[threadIdx.x + off];
            s1[threadIdx.x] += s1[threadIdx.x + off];
        }
        __syncthreads();
    }
    if (threadIdx.x == 0) {
        out[b * 2 + 0] = s0[0] + bias[0];
        out[b * 2 + 1] = s1[0] + bias[1];
    }
}

// ---------------------------------------------------------------------------
extern "C" void kernel_launch(void* const* d_in, const int* in_sizes, int n_in,
                              void* d_out, int out_size) {
    const int*   cue      = (const int*)d_in[0];     // bool -> int32 in harness
    const float* ec3_last = (const float*)d_in[1];
    const float* ec5_last = (const float*)d_in[2];
    const float* ca1_last = (const float*)d_in[3];
    const float* ca1bias  = (const float*)d_in[4];
    const float* wca3ca1  = (const float*)d_in[5];
    const float* wec3ca1  = (const float*)d_in[6];
    const float* wca1ec5  = (const float*)d_in[7];
    const float* wca1act  = (const float*)d_in[8];
    const float* actbias  = (const float*)d_in[9];

    float* out = (float*)d_out;
    float* act = out + OFF_ACT;
    float* e3h = out + OFF_E3H;
    float* e5h = out + OFF_E5H;
    float* c1h = out + OFF_C1H;
    float* ec3 = out + OFF_EC3;
    float* ec5 = out + OFF_EC5;
    float* ca1 = out + OFF_CA1;

    // Recurrent state lives directly in its d_out slots.
    cudaMemcpyAsync(ec3, ec3_last, (size_t)BSZ * NDIM * sizeof(float), cudaMemcpyDeviceToDevice);
    cudaMemcpyAsync(ec5, ec5_last, (size_t)BSZ * NDIM * sizeof(float), cudaMemcpyDeviceToDevice);
    cudaMemcpyAsync(ca1, ca1_last, (size_t)BSZ * NDIM * sizeof(float), cudaMemcpyDeviceToDevice);

    keys_kernel<<<1, 128>>>();
    drive_kernel<<<TLEN, 256>>>(wca3ca1);

    dim3 grid(NDIM / 64, BSZ / 64), blk(256);
    for (int t = 0; t < TLEN; t++) {
        step1_kernel<<<grid, blk>>>(ec3, wec3ca1, ca1bias, ca1, c1h, t);
        step2_kernel<<<grid, blk>>>(ca1, wca1ec5, cue, ec3, ec5, e3h, e5h, t);
    }
    act_kernel<<<BSZ, 128>>>(ca1, wca1act, actbias, act);
}

// round 7
// speedup vs baseline: 2.3316x; 2.3316x over previous
#include <cuda_runtime.h>
#include <stdint.h>

#define BSZ   1024
#define NDIM  1024
#define TLEN  100

// d_out layout (float elements)
#define OFF_ACT 0
#define OFF_E3H 2048
#define OFF_E5H (2048 + 102400)
#define OFF_C1H (2048 + 2*102400)
#define OFF_EC3 (2048 + 3*102400)
#define OFF_EC5 (OFF_EC3 + 1048576)
#define OFF_CA1 (OFF_EC5 + 1048576)

__device__ float    g_drive[TLEN * NDIM];
__device__ uint32_t g_keys[2 * TLEN];
__device__ float    g_wt1[NDIM * NDIM];   // wec3ca1^T [n][k], tf32-rounded
__device__ float    g_wt2[NDIM * NDIM];   // wca1ec5^T [n][k], tf32-rounded

// GEMM tiling: block 128(M) x 64(N), K-tile 32. 8 warps as 4(m) x 2(n),
// warp tile 32x32 of m16n8k8 mma. Smem pitch 36 floats -> conflict-free LDS.
#define PITCH 36
#define AS_BUF 4608       // 128*36 floats
#define BS_BUF 2304       // 64*36 floats
#define SM_FLOATS (2*AS_BUF + 2*BS_BUF)
#define SMEM_DYN (SM_FLOATS * 4)   // 55296 bytes

// TF32 input rounding (round-to-nearest) — matches reference TF32 GEMM inputs.
__device__ __forceinline__ float tf32r(float x) {
    uint32_t u = __float_as_uint(x);
    asm("cvt.rna.tf32.f32 %0, %0;" : "+r"(u));
    return __uint_as_float(u);
}
__device__ __forceinline__ float sigmoidf(float x) { return 1.0f / (1.0f + expf(-x)); }

__device__ __forceinline__ void mma8(float c[4], const uint32_t a[4], const uint32_t b[2]) {
    asm volatile(
        "mma.sync.aligned.m16n8k8.row.col.f32.tf32.tf32.f32 "
        "{%0,%1,%2,%3}, {%4,%5,%6,%7}, {%8,%9}, {%0,%1,%2,%3};"
        : "+f"(c[0]), "+f"(c[1]), "+f"(c[2]), "+f"(c[3])
        : "r"(a[0]), "r"(a[1]), "r"(a[2]), "r"(a[3]), "r"(b[0]), "r"(b[1]));
}

// ---------------------------------------------------------------------------
// Threefry-2x32 (jax partitionable) — validated round 5
// ---------------------------------------------------------------------------
__device__ __forceinline__ void threefry2x32(uint32_t k0, uint32_t k1,
                                             uint32_t x0, uint32_t x1,
                                             uint32_t& o0, uint32_t& o1) {
    uint32_t ks2 = k0 ^ k1 ^ 0x1BD11BDAu;
    x0 += k0; x1 += k1;
#define TF_R(r) { x0 += x1; x1 = __funnelshift_l(x1, x1, (r)); x1 ^= x0; }
    TF_R(13) TF_R(15) TF_R(26) TF_R(6)
    x0 += k1;  x1 += ks2 + 1u;
    TF_R(17) TF_R(29) TF_R(16) TF_R(24)
    x0 += ks2; x1 += k0 + 2u;
    TF_R(13) TF_R(15) TF_R(26) TF_R(6)
    x0 += k0;  x1 += k1 + 3u;
    TF_R(17) TF_R(29) TF_R(16) TF_R(24)
    x0 += k1;  x1 += ks2 + 4u;
    TF_R(13) TF_R(15) TF_R(26) TF_R(6)
    x0 += ks2; x1 += k0 + 5u;
#undef TF_R
    o0 = x0; o1 = x1;
}

__global__ void keys_kernel() {
    int t = threadIdx.x;
    if (t < TLEN) {
        uint32_t o0, o1;
        threefry2x32(0u, 42u, 0u, (uint32_t)t, o0, o1);
        g_keys[2 * t] = o0; g_keys[2 * t + 1] = o1;
    }
}

__device__ __forceinline__ bool noise_hit(uint32_t k0, uint32_t k1, uint32_t idx) {
    uint32_t o0, o1;
    threefry2x32(k0, k1, 0u, idx, o0, o1);
    uint32_t bits = o0 ^ o1;
    float u = __uint_as_float((bits >> 9) | 0x3f800000u) - 1.0f;
    return u < 0.004f;
}

// ---------------------------------------------------------------------------
// drive_all precompute (validated)
// ---------------------------------------------------------------------------
__global__ __launch_bounds__(256) void drive_kernel(const float* __restrict__ wca3ca1) {
    __shared__ float ca3[NDIM];
    const int t = blockIdx.x;
    const float x = (float)t;
    for (int c = threadIdx.x; c < NDIM; c += 256) {
        float center = (100.0f / 1023.0f) * (float)c;
        float d = center - x;
        ca3[c] = tf32r(expf(-(d * d) / 50.0f));
    }
    __syncthreads();
    for (int n = threadIdx.x; n < NDIM; n += 256) {
        float acc = 0.0f;
        for (int k = 0; k < NDIM; k++)
            acc += ca3[k] * tf32r(wca3ca1[k * NDIM + n]);
        g_drive[t * NDIM + n] = acc;
    }
}

// ---------------------------------------------------------------------------
// One-time weight transpose + tf32 rounding: Wt[n][k] = tf32(W[k][n])
// ---------------------------------------------------------------------------
__global__ void transpose_kernel(const float* __restrict__ W, int which) {
    __shared__ float tile[32][33];
    float* dst = which ? g_wt2 : g_wt1;
    int bx = blockIdx.x * 32, by = blockIdx.y * 32;
    int x = threadIdx.x, y = threadIdx.y;   // 32 x 8
#pragma unroll
    for (int i = 0; i < 32; i += 8)
        tile[y + i][x] = tf32r(W[(size_t)(by + y + i) * NDIM + bx + x]);
    __syncthreads();
#pragma unroll
    for (int i = 0; i < 32; i += 8)
        dst[(size_t)(bx + y + i) * NDIM + by + x] = tile[x][y + i];
}

// ---------------------------------------------------------------------------
// Core GEMM: acc[2][4][4] = tf32 MMA of A[128 rows] x Bt^T[64 cols], K=1024.
// ---------------------------------------------------------------------------
__device__ __forceinline__ void gemm_mma_tf32(
    const float* __restrict__ A, const float* __restrict__ Bt,
    float* sm, float acc[2][4][4])
{
    const int tid  = threadIdx.x;
    const int lane = tid & 31, warp = tid >> 5;
    const int group = lane >> 2, tig = lane & 3;
    const int wm = warp & 3, wn = warp >> 2;
    const int m0 = blockIdx.y * 128, n0 = blockIdx.x * 64;

    float* As = sm;              // 2 x AS_BUF
    float* Bs = sm + 2 * AS_BUF; // 2 x BS_BUF

    const int lrow = tid >> 3;
    const int lcol = (tid & 7) * 4;
    const float* ag = A  + (size_t)(m0 + lrow) * NDIM + lcol;
    const float* bg = Bt + (size_t)(n0 + lrow) * NDIM + lcol;

#pragma unroll
    for (int mi = 0; mi < 2; mi++)
#pragma unroll
        for (int nj = 0; nj < 4; nj++)
#pragma unroll
            for (int c = 0; c < 4; c++) acc[mi][nj][c] = 0.0f;

    float4 pa[4], pb[2];
#pragma unroll
    for (int i = 0; i < 4; i++) pa[i] = *(const float4*)(ag + (size_t)i * 32 * NDIM);
#pragma unroll
    for (int i = 0; i < 2; i++) pb[i] = *(const float4*)(bg + (size_t)i * 32 * NDIM);

    // store tile 0 into buf 0 (A rounded to tf32 here; B pre-rounded)
    {
        float* as = As; float* bs = Bs;
#pragma unroll
        for (int i = 0; i < 4; i++) {
            float4 v = pa[i];
            v.x = tf32r(v.x); v.y = tf32r(v.y); v.z = tf32r(v.z); v.w = tf32r(v.w);
            *(float4*)(as + (lrow + 32 * i) * PITCH + lcol) = v;
        }
#pragma unroll
        for (int i = 0; i < 2; i++)
            *(float4*)(bs + (lrow + 32 * i) * PITCH + lcol) = pb[i];
    }
    __syncthreads();

    for (int kt = 0; kt < 32; kt++) {
        const int buf = kt & 1;
        if (kt + 1 < 32) {
            const float* ag2 = ag + (kt + 1) * 32;
            const float* bg2 = bg + (kt + 1) * 32;
#pragma unroll
            for (int i = 0; i < 4; i++) pa[i] = *(const float4*)(ag2 + (size_t)i * 32 * NDIM);
#pragma unroll
            for (int i = 0; i < 2; i++) pb[i] = *(const float4*)(bg2 + (size_t)i * 32 * NDIM);
        }

        // compute on buf
        {
            const float* as = As + buf * AS_BUF;
            const float* bs = Bs + buf * BS_BUF;
#pragma unroll
            for (int kk = 0; kk < 4; kk++) {
                uint32_t af[2][4], bf[4][2];
#pragma unroll
                for (int mi = 0; mi < 2; mi++) {
                    const int rb = wm * 32 + mi * 16;
                    af[mi][0] = __float_as_uint(as[(rb + group)     * PITCH + kk * 8 + tig]);
                    af[mi][1] = __float_as_uint(as[(rb + group + 8) * PITCH + kk * 8 + tig]);
                    af[mi][2] = __float_as_uint(as[(rb + group)     * PITCH + kk * 8 + tig + 4]);
                    af[mi][3] = __float_as_uint(as[(rb + group + 8) * PITCH + kk * 8 + tig + 4]);
                }
#pragma unroll
                for (int nj = 0; nj < 4; nj++) {
                    const int rb = wn * 32 + nj * 8;
                    bf[nj][0] = __float_as_uint(bs[(rb + group) * PITCH + kk * 8 + tig]);
                    bf[nj][1] = __float_as_uint(bs[(rb + group) * PITCH + kk * 8 + tig + 4]);
                }
#pragma unroll
                for (int mi = 0; mi < 2; mi++)
#pragma unroll
                    for (int nj = 0; nj < 4; nj++)
                        mma8(acc[mi][nj], af[mi], bf[nj]);
            }
        }

        if (kt + 1 < 32) {
            float* as = As + ((kt + 1) & 1) * AS_BUF;
            float* bs = Bs + ((kt + 1) & 1) * BS_BUF;
#pragma unroll
            for (int i = 0; i < 4; i++) {
                float4 v = pa[i];
                v.x = tf32r(v.x); v.y = tf32r(v.y); v.z = tf32r(v.z); v.w = tf32r(v.w);
                *(float4*)(as + (lrow + 32 * i) * PITCH + lcol) = v;
            }
#pragma unroll
            for (int i = 0; i < 2; i++)
                *(float4*)(bs + (lrow + 32 * i) * PITCH + lcol) = pb[i];
        }
        __syncthreads();
    }
}

// ---------------------------------------------------------------------------
// step1: ca1 = relu(drive_t * (1 + sigmoid(ec3 @ wec3ca1)) - ca1bias)
// ---------------------------------------------------------------------------
__global__ __launch_bounds__(256) void step1_mma(
    const float* __restrict__ ec3, const float* __restrict__ ca1bias,
    float* __restrict__ ca1, float* __restrict__ c1h, int t)
{
    extern __shared__ float sm[];
    float acc[2][4][4];
    gemm_mma_tf32(ec3, g_wt1, sm, acc);

    const int lane = threadIdx.x & 31, warp = threadIdx.x >> 5;
    const int group = lane >> 2, tig = lane & 3;
    const int wm = warp & 3, wn = warp >> 2;
    const int m0 = blockIdx.y * 128, n0 = blockIdx.x * 64;
    const float* drive = &g_drive[t * NDIM];

#pragma unroll
    for (int mi = 0; mi < 2; mi++)
#pragma unroll
        for (int nj = 0; nj < 4; nj++)
#pragma unroll
            for (int c = 0; c < 4; c++) {
                const int m = m0 + wm * 32 + mi * 16 + group + ((c & 2) ? 8 : 0);
                const int n = n0 + wn * 32 + nj * 8 + tig * 2 + (c & 1);
                float v = fmaxf(drive[n] * (1.0f + sigmoidf(acc[mi][nj][c])) - ca1bias[n], 0.0f);
                ca1[m * NDIM + n] = v;
                if (m == 0) c1h[t * NDIM + n] = v;
            }
}

// ---------------------------------------------------------------------------
// step2: ec5 += ca1 @ wca1ec5; squash; ec3 *= ec5; cue @ t==10; threefry noise
// ---------------------------------------------------------------------------
__global__ __launch_bounds__(256) void step2_mma(
    const float* __restrict__ ca1, const int* __restrict__ cue,
    float* __restrict__ ec3, float* __restrict__ ec5,
    float* __restrict__ e3h, float* __restrict__ e5h, int t)
{
    extern __shared__ float sm[];
    float acc[2][4][4];
    gemm_mma_tf32(ca1, g_wt2, sm, acc);

    const int lane = threadIdx.x & 31, warp = threadIdx.x >> 5;
    const int group = lane >> 2, tig = lane & 3;
    const int wm = warp & 3, wn = warp >> 2;
    const int m0 = blockIdx.y * 128, n0 = blockIdx.x * 64;
    const uint32_t k0 = g_keys[2 * t], k1 = g_keys[2 * t + 1];
    const bool at_cue = (t == 10);

#pragma unroll
    for (int mi = 0; mi < 2; mi++)
#pragma unroll
        for (int nj = 0; nj < 4; nj++)
#pragma unroll
            for (int c = 0; c < 4; c++) {
                const int m = m0 + wm * 32 + mi * 16 + group + ((c & 2) ? 8 : 0);
                const int n = n0 + wn * 32 + nj * 8 + tig * 2 + (c & 1);
                const int gi = m * NDIM + n;
                float e5 = ec5[gi] + acc[mi][nj][c];       // 10*TS == 1.0 exactly
                e5 = 0.69f + 0.3f * sigmoidf(4.0f * (e5 - 0.3f));
                float e3 = e5 * ec3[gi];
                if (at_cue && (cue[gi] != 0)) e3 = 0.4f * e3 + 0.6f;
                if (noise_hit(k0, k1, (uint32_t)gi)) e3 = 0.5f * e3 + 0.3f;
                ec5[gi] = e5;
                ec3[gi] = e3;
                if (m == 0) { e5h[t * NDIM + n] = e5; e3h[t * NDIM + n] = e3; }
            }
}

// ---------------------------------------------------------------------------
// act_cell = ca1 @ wca1act + actbias (tf32 operands, validated)
// ---------------------------------------------------------------------------
__global__ __launch_bounds__(128) void act_kernel(
    const float* __restrict__ ca1, const float* __restrict__ w,
    const float* __restrict__ bias, float* __restrict__ out)
{
    __shared__ float s0[128], s1[128];
    const int b = blockIdx.x;
    float a0 = 0.0f, a1 = 0.0f;
    for (int c = threadIdx.x; c < NDIM; c += 128) {
        float v = tf32r(ca1[b * NDIM + c]);
        a0 += v * tf32r(w[c * 2 + 0]);
        a1 += v * tf32r(w[c * 2 + 1]);
    }
    s0[threadIdx.x] = a0; s1[threadIdx.x] = a1;
    __syncthreads();
    for (int off = 64; off > 0; off >>= 1) {
        if (threadIdx.x < off) {
            s0[threadIdx.x] += s0[threadIdx.x + off];
            s1[threadIdx.x] += s1[threadIdx.x + off];
        }
        __syncthreads();
    }
    if (threadIdx.x == 0) {
        out[b * 2 + 0] = s0[0] + bias[0];
        out[b * 2 + 1] = s1[0] + bias[1];
    }
}

// ---------------------------------------------------------------------------
extern "C" void kernel_launch(void* const* d_in, const int* in_sizes, int n_in,
                              void* d_out, int out_size) {
    const int*   cue      = (const int*)d_in[0];     // bool -> int32 in harness
    const float* ec3_last = (const float*)d_in[1];
    const float* ec5_last = (const float*)d_in[2];
    const float* ca1_last = (const float*)d_in[3];
    const float* ca1bias  = (const float*)d_in[4];
    const float* wca3ca1  = (const float*)d_in[5];
    const float* wec3ca1  = (const float*)d_in[6];
    const float* wca1ec5  = (const float*)d_in[7];
    const float* wca1act  = (const float*)d_in[8];
    const float* actbias  = (const float*)d_in[9];

    float* out = (float*)d_out;
    float* act = out + OFF_ACT;
    float* e3h = out + OFF_E3H;
    float* e5h = out + OFF_E5H;
    float* c1h = out + OFF_C1H;
    float* ec3 = out + OFF_EC3;
    float* ec5 = out + OFF_EC5;
    float* ca1 = out + OFF_CA1;

    static int attr_done = 0;
    if (!attr_done) {
        cudaFuncSetAttribute(step1_mma, cudaFuncAttributeMaxDynamicSharedMemorySize, SMEM_DYN);
        cudaFuncSetAttribute(step2_mma, cudaFuncAttributeMaxDynamicSharedMemorySize, SMEM_DYN);
        attr_done = 1;
    }

    cudaMemcpyAsync(ec3, ec3_last, (size_t)BSZ * NDIM * sizeof(float), cudaMemcpyDeviceToDevice);
    cudaMemcpyAsync(ec5, ec5_last, (size_t)BSZ * NDIM * sizeof(float), cudaMemcpyDeviceToDevice);
    cudaMemcpyAsync(ca1, ca1_last, (size_t)BSZ * NDIM * sizeof(float), cudaMemcpyDeviceToDevice);

    keys_kernel<<<1, 128>>>();
    drive_kernel<<<TLEN, 256>>>(wca3ca1);
    transpose_kernel<<<dim3(32, 32), dim3(32, 8)>>>(wec3ca1, 0);
    transpose_kernel<<<dim3(32, 32), dim3(32, 8)>>>(wca1ec5, 1);

    dim3 grid(NDIM / 64, BSZ / 128);
    for (int t = 0; t < TLEN; t++) {
        step1_mma<<<grid, 256, SMEM_DYN>>>(ec3, ca1bias, ca1, c1h, t);
        step2_mma<<<grid, 256, SMEM_DYN>>>(ca1, cue, ec3, ec5, e3h, e5h, t);
    }
    act_kernel<<<BSZ, 128>>>(ca1, wca1act, actbias, act);
}

// round 8
// speedup vs baseline: 2.6995x; 1.1578x over previous
#include <cuda_runtime.h>
#include <stdint.h>

#define BSZ   1024
#define NDIM  1024
#define TLEN  100

// d_out layout (float elements)
#define OFF_ACT 0
#define OFF_E3H 2048
#define OFF_E5H (2048 + 102400)
#define OFF_C1H (2048 + 2*102400)
#define OFF_EC3 (2048 + 3*102400)
#define OFF_EC5 (OFF_EC3 + 1048576)
#define OFF_CA1 (OFF_EC5 + 1048576)

__device__ float    g_drive[TLEN * NDIM];
__device__ uint32_t g_keys[2 * TLEN];
__device__ float    g_wt1[NDIM * NDIM];   // wec3ca1^T [n][k], tf32-rounded
__device__ float    g_wt2[NDIM * NDIM];   // wca1ec5^T [n][k], tf32-rounded
__device__ float    g_at1[NDIM * NDIM];   // tf32-rounded ec3 (A of step1)
__device__ float    g_at2[NDIM * NDIM];   // tf32-rounded ca1 (A of step2)

// GEMM tiling: block 128(M) x 64(N), K-tile 32, 8 warps 4(m)x2(n), warp 32x32.
// cp.async 3-stage pipeline; ldmatrix.x4 fragment loads. PITCH 36 floats.
#define PITCH 36
#define STAGE_A_BYTES (128 * PITCH * 4)          // 18432
#define STAGE_BYTES   (192 * PITCH * 4)          // 27648
#define NSTAGE 3
#define SMEM_DYN (NSTAGE * STAGE_BYTES)          // 82944

// ---------------------------------------------------------------------------
__device__ __forceinline__ float tf32r(float x) {
    uint32_t u = __float_as_uint(x);
    asm("cvt.rna.tf32.f32 %0, %0;" : "+r"(u));
    return __uint_as_float(u);
}
__device__ __forceinline__ float sigmoidf(float x) { return 1.0f / (1.0f + expf(-x)); }
__device__ __forceinline__ uint32_t smem_to_u32(const void* p) {
    uint32_t a;
    asm("{ .reg .u64 t; cvta.to.shared.u64 t, %1; cvt.u32.u64 %0, t; }" : "=r"(a) : "l"(p));
    return a;
}
__device__ __forceinline__ void cp16(uint32_t dst, const void* src) {
    asm volatile("cp.async.cg.shared.global [%0], [%1], 16;" :: "r"(dst), "l"(src));
}
__device__ __forceinline__ void cp_commit() { asm volatile("cp.async.commit_group;"); }
__device__ __forceinline__ void ldsm4(uint32_t r[4], uint32_t addr) {
    asm volatile("ldmatrix.sync.aligned.m8n8.x4.shared.b16 {%0,%1,%2,%3}, [%4];"
        : "=r"(r[0]), "=r"(r[1]), "=r"(r[2]), "=r"(r[3]) : "r"(addr));
}
__device__ __forceinline__ void mma8(float c[4], const uint32_t a[4], const uint32_t b[2]) {
    asm volatile(
        "mma.sync.aligned.m16n8k8.row.col.f32.tf32.tf32.f32 "
        "{%0,%1,%2,%3}, {%4,%5,%6,%7}, {%8,%9}, {%0,%1,%2,%3};"
        : "+f"(c[0]), "+f"(c[1]), "+f"(c[2]), "+f"(c[3])
        : "r"(a[0]), "r"(a[1]), "r"(a[2]), "r"(a[3]), "r"(b[0]), "r"(b[1]));
}

// ---------------------------------------------------------------------------
// Threefry-2x32 (jax partitionable) — validated
// ---------------------------------------------------------------------------
__device__ __forceinline__ void threefry2x32(uint32_t k0, uint32_t k1,
                                             uint32_t x0, uint32_t x1,
                                             uint32_t& o0, uint32_t& o1) {
    uint32_t ks2 = k0 ^ k1 ^ 0x1BD11BDAu;
    x0 += k0; x1 += k1;
#define TF_R(r) { x0 += x1; x1 = __funnelshift_l(x1, x1, (r)); x1 ^= x0; }
    TF_R(13) TF_R(15) TF_R(26) TF_R(6)
    x0 += k1;  x1 += ks2 + 1u;
    TF_R(17) TF_R(29) TF_R(16) TF_R(24)
    x0 += ks2; x1 += k0 + 2u;
    TF_R(13) TF_R(15) TF_R(26) TF_R(6)
    x0 += k0;  x1 += k1 + 3u;
    TF_R(17) TF_R(29) TF_R(16) TF_R(24)
    x0 += k1;  x1 += ks2 + 4u;
    TF_R(13) TF_R(15) TF_R(26) TF_R(6)
    x0 += ks2; x1 += k0 + 5u;
#undef TF_R
    o0 = x0; o1 = x1;
}

__global__ void keys_kernel() {
    int t = threadIdx.x;
    if (t < TLEN) {
        uint32_t o0, o1;
        threefry2x32(0u, 42u, 0u, (uint32_t)t, o0, o1);
        g_keys[2 * t] = o0; g_keys[2 * t + 1] = o1;
    }
}

__device__ __forceinline__ bool noise_hit(uint32_t k0, uint32_t k1, uint32_t idx) {
    uint32_t o0, o1;
    threefry2x32(k0, k1, 0u, idx, o0, o1);
    uint32_t bits = o0 ^ o1;
    float u = __uint_as_float((bits >> 9) | 0x3f800000u) - 1.0f;
    return u < 0.004f;
}

// ---------------------------------------------------------------------------
// drive_all precompute (validated)
// ---------------------------------------------------------------------------
__global__ __launch_bounds__(256) void drive_kernel(const float* __restrict__ wca3ca1) {
    __shared__ float ca3[NDIM];
    const int t = blockIdx.x;
    const float x = (float)t;
    for (int c = threadIdx.x; c < NDIM; c += 256) {
        float center = (100.0f / 1023.0f) * (float)c;
        float d = center - x;
        ca3[c] = tf32r(expf(-(d * d) / 50.0f));
    }
    __syncthreads();
    for (int n = threadIdx.x; n < NDIM; n += 256) {
        float acc = 0.0f;
        for (int k = 0; k < NDIM; k++)
            acc += ca3[k] * tf32r(wca3ca1[k * NDIM + n]);
        g_drive[t * NDIM + n] = acc;
    }
}

// One-time weight transpose + tf32 rounding: Wt[n][k] = tf32(W[k][n])
__global__ void transpose_kernel(const float* __restrict__ W, int which) {
    __shared__ float tile[32][33];
    float* dst = which ? g_wt2 : g_wt1;
    int bx = blockIdx.x * 32, by = blockIdx.y * 32;
    int x = threadIdx.x, y = threadIdx.y;   // 32 x 8
#pragma unroll
    for (int i = 0; i < 32; i += 8)
        tile[y + i][x] = tf32r(W[(size_t)(by + y + i) * NDIM + bx + x]);
    __syncthreads();
#pragma unroll
    for (int i = 0; i < 32; i += 8)
        dst[(size_t)(bx + y + i) * NDIM + by + x] = tile[x][y + i];
}

// One-time: g_at1 = tf32r(ec3_last)
__global__ __launch_bounds__(256) void round_init_kernel(const float* __restrict__ src) {
    int i = (blockIdx.x * 256 + threadIdx.x) * 4;
    float4 v = *(const float4*)(src + i);
    v.x = tf32r(v.x); v.y = tf32r(v.y); v.z = tf32r(v.z); v.w = tf32r(v.w);
    *(float4*)(g_at1 + i) = v;
}

// ---------------------------------------------------------------------------
// GEMM core: acc[2][4][4] += A(pre-tf32)[128 x 1024] @ Bt(pre-tf32)^T, N-tile 64.
// cp.async 3-stage, ldmatrix fragments.
// ---------------------------------------------------------------------------
__device__ __forceinline__ void issue_tile(
    const float* __restrict__ A, const float* __restrict__ Bt,
    int m0, int n0, int kt, int stage, uint32_t sb, int tid)
{
    const int row = tid >> 3, col4 = (tid & 7) * 4;
    const float* ag = A + (size_t)(m0 + row) * NDIM + kt * 32 + col4;
    uint32_t ad = sb + stage * STAGE_BYTES + (row * PITCH + col4) * 4;
#pragma unroll
    for (int i = 0; i < 4; i++)
        cp16(ad + i * 32 * PITCH * 4, ag + (size_t)i * 32 * NDIM);
    const float* bg = Bt + (size_t)(n0 + row) * NDIM + kt * 32 + col4;
    uint32_t bd = sb + stage * STAGE_BYTES + STAGE_A_BYTES + (row * PITCH + col4) * 4;
#pragma unroll
    for (int i = 0; i < 2; i++)
        cp16(bd + i * 32 * PITCH * 4, bg + (size_t)i * 32 * NDIM);
    cp_commit();
}

__device__ __forceinline__ void gemm_mma_tf32(
    const float* __restrict__ A, const float* __restrict__ Bt,
    float* sm, float acc[2][4][4])
{
    const int tid  = threadIdx.x;
    const int lane = tid & 31, warp = tid >> 5;
    const int wm = warp & 3, wn = warp >> 2;
    const int m0 = blockIdx.y * 128, n0 = blockIdx.x * 64;
    const uint32_t sb = smem_to_u32(sm);

    // ldmatrix per-lane address offsets (bytes within a stage)
    const int q = lane >> 3, r = lane & 7;
    uint32_t aoff[2], boff[2];
#pragma unroll
    for (int mi = 0; mi < 2; mi++) {
        int rowA = wm * 32 + mi * 16 + r + ((q & 1) ? 8 : 0);
        int colA = (q & 2) ? 4 : 0;
        aoff[mi] = (uint32_t)((rowA * PITCH + colA) * 4);
    }
#pragma unroll
    for (int j = 0; j < 2; j++) {
        int rowB = wn * 32 + j * 16 + r + ((q & 2) ? 8 : 0);
        int colB = (q & 1) ? 4 : 0;
        boff[j] = (uint32_t)(STAGE_A_BYTES + (rowB * PITCH + colB) * 4);
    }

#pragma unroll
    for (int mi = 0; mi < 2; mi++)
#pragma unroll
        for (int nj = 0; nj < 4; nj++)
#pragma unroll
            for (int c = 0; c < 4; c++) acc[mi][nj][c] = 0.0f;

    issue_tile(A, Bt, m0, n0, 0, 0, sb, tid);
    issue_tile(A, Bt, m0, n0, 1, 1, sb, tid);

    for (int kt = 0; kt < 32; kt++) {
        if (kt < 30) asm volatile("cp.async.wait_group 1;");
        else         asm volatile("cp.async.wait_group 0;");
        __syncthreads();

        const uint32_t st = sb + (uint32_t)(kt % 3) * STAGE_BYTES;
#pragma unroll
        for (int kk = 0; kk < 4; kk++) {
            uint32_t af[2][4], b01[4], b23[4];
            ldsm4(af[0], st + aoff[0] + kk * 32);
            ldsm4(af[1], st + aoff[1] + kk * 32);
            ldsm4(b01,   st + boff[0] + kk * 32);
            ldsm4(b23,   st + boff[1] + kk * 32);
#pragma unroll
            for (int mi = 0; mi < 2; mi++) {
                mma8(acc[mi][0], af[mi], &b01[0]);
                mma8(acc[mi][1], af[mi], &b01[2]);
                mma8(acc[mi][2], af[mi], &b23[0]);
                mma8(acc[mi][3], af[mi], &b23[2]);
            }
        }
        if (kt + 2 < 32)
            issue_tile(A, Bt, m0, n0, kt + 2, (kt + 2) % 3, sb, tid);
    }
}

// ---------------------------------------------------------------------------
// step1: ca1 = relu(drive_t * (1 + sigmoid(ec3 @ wec3ca1)) - ca1bias)
//        also writes ca1_t = tf32r(ca1) scratch for step2's GEMM
// ---------------------------------------------------------------------------
__global__ __launch_bounds__(256) void step1_mma(
    const float* __restrict__ ca1bias,
    float* __restrict__ ca1, float* __restrict__ c1h, int t)
{
    extern __shared__ float sm[];
    float acc[2][4][4];
    gemm_mma_tf32(g_at1, g_wt1, sm, acc);

    const int lane = threadIdx.x & 31, warp = threadIdx.x >> 5;
    const int group = lane >> 2, tig = lane & 3;
    const int wm = warp & 3, wn = warp >> 2;
    const int m0 = blockIdx.y * 128, n0 = blockIdx.x * 64;
    const float* drive = &g_drive[t * NDIM];

#pragma unroll
    for (int mi = 0; mi < 2; mi++)
#pragma unroll
        for (int nj = 0; nj < 4; nj++)
#pragma unroll
            for (int c = 0; c < 4; c++) {
                const int m = m0 + wm * 32 + mi * 16 + group + ((c & 2) ? 8 : 0);
                const int n = n0 + wn * 32 + nj * 8 + tig * 2 + (c & 1);
                float v = fmaxf(drive[n] * (1.0f + sigmoidf(acc[mi][nj][c])) - ca1bias[n], 0.0f);
                const int gi = m * NDIM + n;
                ca1[gi] = v;
                g_at2[gi] = tf32r(v);
                if (m == 0) c1h[t * NDIM + n] = v;
            }
}

// ---------------------------------------------------------------------------
// step2: ec5 += ca1 @ wca1ec5; squash; ec3 *= ec5; cue @ t==10; threefry noise
//        also writes ec3_t = tf32r(ec3) scratch for next step1's GEMM
// ---------------------------------------------------------------------------
__global__ __launch_bounds__(256) void step2_mma(
    const int* __restrict__ cue,
    float* __restrict__ ec3, float* __restrict__ ec5,
    float* __restrict__ e3h, float* __restrict__ e5h, int t)
{
    extern __shared__ float sm[];
    float acc[2][4][4];
    gemm_mma_tf32(g_at2, g_wt2, sm, acc);

    const int lane = threadIdx.x & 31, warp = threadIdx.x >> 5;
    const int group = lane >> 2, tig = lane & 3;
    const int wm = warp & 3, wn = warp >> 2;
    const int m0 = blockIdx.y * 128, n0 = blockIdx.x * 64;
    const uint32_t k0 = g_keys[2 * t], k1 = g_keys[2 * t + 1];
    const bool at_cue = (t == 10);

#pragma unroll
    for (int mi = 0; mi < 2; mi++)
#pragma unroll
        for (int nj = 0; nj < 4; nj++)
#pragma unroll
            for (int c = 0; c < 4; c++) {
                const int m = m0 + wm * 32 + mi * 16 + group + ((c & 2) ? 8 : 0);
                const int n = n0 + wn * 32 + nj * 8 + tig * 2 + (c & 1);
                const int gi = m * NDIM + n;
                float e5 = ec5[gi] + acc[mi][nj][c];       // 10*TS == 1.0 exactly
                e5 = 0.69f + 0.3f * sigmoidf(4.0f * (e5 - 0.3f));
                float e3 = e5 * ec3[gi];
                if (at_cue && (cue[gi] != 0)) e3 = 0.4f * e3 + 0.6f;
                if (noise_hit(k0, k1, (uint32_t)gi)) e3 = 0.5f * e3 + 0.3f;
                ec5[gi] = e5;
                ec3[gi] = e3;
                g_at1[gi] = tf32r(e3);
                if (m == 0) { e5h[t * NDIM + n] = e5; e3h[t * NDIM + n] = e3; }
            }
}

// ---------------------------------------------------------------------------
// act_cell = ca1 @ wca1act + actbias (tf32 operands, validated)
// ---------------------------------------------------------------------------
__global__ __launch_bounds__(128) void act_kernel(
    const float* __restrict__ ca1, const float* __restrict__ w,
    const float* __restrict__ bias, float* __restrict__ out)
{
    __shared__ float s0[128], s1[128];
    const int b = blockIdx.x;
    float a0 = 0.0f, a1 = 0.0f;
    for (int c = threadIdx.x; c < NDIM; c += 128) {
        float v = tf32r(ca1[b * NDIM + c]);
        a0 += v * tf32r(w[c * 2 + 0]);
        a1 += v * tf32r(w[c * 2 + 1]);
    }
    s0[threadIdx.x] = a0; s1[threadIdx.x] = a1;
    __syncthreads();
    for (int off = 64; off > 0; off >>= 1) {
        if (threadIdx.x < off) {
            s0[threadIdx.x] += s0[threadIdx.x + off];
            s1[threadIdx.x] += s1[threadIdx.x + off];
        }
        __syncthreads();
    }
    if (threadIdx.x == 0) {
        out[b * 2 + 0] = s0[0] + bias[0];
        out[b * 2 + 1] = s1[0] + bias[1];
    }
}

// ---------------------------------------------------------------------------
extern "C" void kernel_launch(void* const* d_in, const int* in_sizes, int n_in,
                              void* d_out, int out_size) {
    const int*   cue      = (const int*)d_in[0];     // bool -> int32 in harness
    const float* ec3_last = (const float*)d_in[1];
    const float* ec5_last = (const float*)d_in[2];
    const float* ca1_last = (const float*)d_in[3];
    const float* ca1bias  = (const float*)d_in[4];
    const float* wca3ca1  = (const float*)d_in[5];
    const float* wec3ca1  = (const float*)d_in[6];
    const float* wca1ec5  = (const float*)d_in[7];
    const float* wca1act  = (const float*)d_in[8];
    const float* actbias  = (const float*)d_in[9];

    float* out = (float*)d_out;
    float* act = out + OFF_ACT;
    float* e3h = out + OFF_E3H;
    float* e5h = out + OFF_E5H;
    float* c1h = out + OFF_C1H;
    float* ec3 = out + OFF_EC3;
    float* ec5 = out + OFF_EC5;
    float* ca1 = out + OFF_CA1;

    static int attr_done = 0;
    if (!attr_done) {
        cudaFuncSetAttribute(step1_mma, cudaFuncAttributeMaxDynamicSharedMemorySize, SMEM_DYN);
        cudaFuncSetAttribute(step2_mma, cudaFuncAttributeMaxDynamicSharedMemorySize, SMEM_DYN);
        attr_done = 1;
    }

    cudaMemcpyAsync(ec3, ec3_last, (size_t)BSZ * NDIM * sizeof(float), cudaMemcpyDeviceToDevice);
    cudaMemcpyAsync(ec5, ec5_last, (size_t)BSZ * NDIM * sizeof(float), cudaMemcpyDeviceToDevice);
    cudaMemcpyAsync(ca1, ca1_last, (size_t)BSZ * NDIM * sizeof(float), cudaMemcpyDeviceToDevice);

    keys_kernel<<<1, 128>>>();
    drive_kernel<<<TLEN, 256>>>(wca3ca1);
    transpose_kernel<<<dim3(32, 32), dim3(32, 8)>>>(wec3ca1, 0);
    transpose_kernel<<<dim3(32, 32), dim3(32, 8)>>>(wca1ec5, 1);
    round_init_kernel<<<BSZ * NDIM / 1024, 256>>>(ec3_last);

    dim3 grid(NDIM / 64, BSZ / 128);
    for (int t = 0; t < TLEN; t++) {
        step1_mma<<<grid, 256, SMEM_DYN>>>(ca1bias, ca1, c1h, t);
        step2_mma<<<grid, 256, SMEM_DYN>>>(cue, ec3, ec5, e3h, e5h, t);
    }
    act_kernel<<<BSZ, 128>>>(ca1, wca1act, actbias, act);
}

// round 9
// speedup vs baseline: 2.7534x; 1.0200x over previous
#include <cuda_runtime.h>
#include <stdint.h>

#define BSZ   1024
#define NDIM  1024
#define TLEN  100

// d_out layout (float elements)
#define OFF_ACT 0
#define OFF_E3H 2048
#define OFF_E5H (2048 + 102400)
#define OFF_C1H (2048 + 2*102400)
#define OFF_EC3 (2048 + 3*102400)
#define OFF_EC5 (OFF_EC3 + 1048576)
#define OFF_CA1 (OFF_EC5 + 1048576)

__device__ float    g_drive[TLEN * NDIM];
__device__ uint32_t g_keys[2 * TLEN];
__device__ float    g_wt1[NDIM * NDIM];   // wec3ca1^T [n][k], tf32-rounded
__device__ float    g_wt2[NDIM * NDIM];   // wca1ec5^T [n][k], tf32-rounded
__device__ float    g_at1[NDIM * NDIM];   // tf32-rounded ec3 (A of step1)
__device__ float    g_at2[NDIM * NDIM];   // tf32-rounded ca1 (A of step2)

// GEMM tiling: block 128(M) x 64(N), K-tile 64 (16 mainloop iterations),
// 8 warps 4(m)x2(n), warp tile 32x32. cp.async 3-stage; ldmatrix.x4 fragments.
#define KTILE  64
#define KTILES 16
#define PITCH  68                                // 64 + 4 pad; 68 mod 32 = 4 -> conflict-free ldsm
#define STAGE_A_BYTES (128 * PITCH * 4)          // 34816
#define STAGE_BYTES   (192 * PITCH * 4)          // 52224
#define NSTAGE 3
#define SMEM_DYN (NSTAGE * STAGE_BYTES)          // 156672

// ---------------------------------------------------------------------------
__device__ __forceinline__ float tf32r(float x) {
    uint32_t u = __float_as_uint(x);
    asm("cvt.rna.tf32.f32 %0, %0;" : "+r"(u));
    return __uint_as_float(u);
}
__device__ __forceinline__ float sigmoidf(float x) { return 1.0f / (1.0f + expf(-x)); }
__device__ __forceinline__ uint32_t smem_to_u32(const void* p) {
    uint32_t a;
    asm("{ .reg .u64 t; cvta.to.shared.u64 t, %1; cvt.u32.u64 %0, t; }" : "=r"(a) : "l"(p));
    return a;
}
__device__ __forceinline__ void cp16(uint32_t dst, const void* src) {
    asm volatile("cp.async.cg.shared.global [%0], [%1], 16;" :: "r"(dst), "l"(src));
}
__device__ __forceinline__ void cp_commit() { asm volatile("cp.async.commit_group;"); }
__device__ __forceinline__ void ldsm4(uint32_t r[4], uint32_t addr) {
    asm volatile("ldmatrix.sync.aligned.m8n8.x4.shared.b16 {%0,%1,%2,%3}, [%4];"
        : "=r"(r[0]), "=r"(r[1]), "=r"(r[2]), "=r"(r[3]) : "r"(addr));
}
__device__ __forceinline__ void mma8(float c[4], const uint32_t a[4], const uint32_t b[2]) {
    asm volatile(
        "mma.sync.aligned.m16n8k8.row.col.f32.tf32.tf32.f32 "
        "{%0,%1,%2,%3}, {%4,%5,%6,%7}, {%8,%9}, {%0,%1,%2,%3};"
        : "+f"(c[0]), "+f"(c[1]), "+f"(c[2]), "+f"(c[3])
        : "r"(a[0]), "r"(a[1]), "r"(a[2]), "r"(a[3]), "r"(b[0]), "r"(b[1]));
}

// ---------------------------------------------------------------------------
// Threefry-2x32 (jax partitionable) — validated
// ---------------------------------------------------------------------------
__device__ __forceinline__ void threefry2x32(uint32_t k0, uint32_t k1,
                                             uint32_t x0, uint32_t x1,
                                             uint32_t& o0, uint32_t& o1) {
    uint32_t ks2 = k0 ^ k1 ^ 0x1BD11BDAu;
    x0 += k0; x1 += k1;
#define TF_R(r) { x0 += x1; x1 = __funnelshift_l(x1, x1, (r)); x1 ^= x0; }
    TF_R(13) TF_R(15) TF_R(26) TF_R(6)
    x0 += k1;  x1 += ks2 + 1u;
    TF_R(17) TF_R(29) TF_R(16) TF_R(24)
    x0 += ks2; x1 += k0 + 2u;
    TF_R(13) TF_R(15) TF_R(26) TF_R(6)
    x0 += k0;  x1 += k1 + 3u;
    TF_R(17) TF_R(29) TF_R(16) TF_R(24)
    x0 += k1;  x1 += ks2 + 4u;
    TF_R(13) TF_R(15) TF_R(26) TF_R(6)
    x0 += ks2; x1 += k0 + 5u;
#undef TF_R
    o0 = x0; o1 = x1;
}

__global__ void keys_kernel() {
    int t = threadIdx.x;
    if (t < TLEN) {
        uint32_t o0, o1;
        threefry2x32(0u, 42u, 0u, (uint32_t)t, o0, o1);
        g_keys[2 * t] = o0; g_keys[2 * t + 1] = o1;
    }
}

__device__ __forceinline__ bool noise_hit(uint32_t k0, uint32_t k1, uint32_t idx) {
    uint32_t o0, o1;
    threefry2x32(k0, k1, 0u, idx, o0, o1);
    uint32_t bits = o0 ^ o1;
    float u = __uint_as_float((bits >> 9) | 0x3f800000u) - 1.0f;
    return u < 0.004f;
}

// ---------------------------------------------------------------------------
// drive_all precompute (validated)
// ---------------------------------------------------------------------------
__global__ __launch_bounds__(256) void drive_kernel(const float* __restrict__ wca3ca1) {
    __shared__ float ca3[NDIM];
    const int t = blockIdx.x;
    const float x = (float)t;
    for (int c = threadIdx.x; c < NDIM; c += 256) {
        float center = (100.0f / 1023.0f) * (float)c;
        float d = center - x;
        ca3[c] = tf32r(expf(-(d * d) / 50.0f));
    }
    __syncthreads();
    for (int n = threadIdx.x; n < NDIM; n += 256) {
        float acc = 0.0f;
        for (int k = 0; k < NDIM; k++)
            acc += ca3[k] * tf32r(wca3ca1[k * NDIM + n]);
        g_drive[t * NDIM + n] = acc;
    }
}

// One-time weight transpose + tf32 rounding: Wt[n][k] = tf32(W[k][n])
__global__ void transpose_kernel(const float* __restrict__ W, int which) {
    __shared__ float tile[32][33];
    float* dst = which ? g_wt2 : g_wt1;
    int bx = blockIdx.x * 32, by = blockIdx.y * 32;
    int x = threadIdx.x, y = threadIdx.y;   // 32 x 8
#pragma unroll
    for (int i = 0; i < 32; i += 8)
        tile[y + i][x] = tf32r(W[(size_t)(by + y + i) * NDIM + bx + x]);
    __syncthreads();
#pragma unroll
    for (int i = 0; i < 32; i += 8)
        dst[(size_t)(bx + y + i) * NDIM + by + x] = tile[x][y + i];
}

// One-time: g_at1 = tf32r(ec3_last)
__global__ __launch_bounds__(256) void round_init_kernel(const float* __restrict__ src) {
    int i = (blockIdx.x * 256 + threadIdx.x) * 4;
    float4 v = *(const float4*)(src + i);
    v.x = tf32r(v.x); v.y = tf32r(v.y); v.z = tf32r(v.z); v.w = tf32r(v.w);
    *(float4*)(g_at1 + i) = v;
}

// ---------------------------------------------------------------------------
// GEMM core: acc[2][4][4] += A(pre-tf32)[128 x 1024] @ Bt(pre-tf32)^T, N-tile 64.
// cp.async 3-stage, K-tile 64, ldmatrix fragments.
// ---------------------------------------------------------------------------
__device__ __forceinline__ void issue_tile(
    const float* __restrict__ A, const float* __restrict__ Bt,
    int m0, int n0, int kt, int stage, uint32_t sb, int tid)
{
    const int row = tid >> 4, col4 = (tid & 15) * 4;
    const float* ag = A + (size_t)(m0 + row) * NDIM + kt * KTILE + col4;
    uint32_t ad = sb + stage * STAGE_BYTES + (row * PITCH + col4) * 4;
#pragma unroll
    for (int i = 0; i < 8; i++)
        cp16(ad + i * 16 * PITCH * 4, ag + (size_t)i * 16 * NDIM);
    const float* bg = Bt + (size_t)(n0 + row) * NDIM + kt * KTILE + col4;
    uint32_t bd = sb + stage * STAGE_BYTES + STAGE_A_BYTES + (row * PITCH + col4) * 4;
#pragma unroll
    for (int i = 0; i < 4; i++)
        cp16(bd + i * 16 * PITCH * 4, bg + (size_t)i * 16 * NDIM);
    cp_commit();
}

__device__ __forceinline__ void gemm_mma_tf32(
    const float* __restrict__ A, const float* __restrict__ Bt,
    float* sm, float acc[2][4][4])
{
    const int tid  = threadIdx.x;
    const int lane = tid & 31, warp = tid >> 5;
    const int wm = warp & 3, wn = warp >> 2;
    const int m0 = blockIdx.y * 128, n0 = blockIdx.x * 64;
    const uint32_t sb = smem_to_u32(sm);

    // ldmatrix per-lane address offsets (bytes within a stage)
    const int q = lane >> 3, r = lane & 7;
    uint32_t aoff[2], boff[2];
#pragma unroll
    for (int mi = 0; mi < 2; mi++) {
        int rowA = wm * 32 + mi * 16 + r + ((q & 1) ? 8 : 0);
        int colA = (q & 2) ? 4 : 0;
        aoff[mi] = (uint32_t)((rowA * PITCH + colA) * 4);
    }
#pragma unroll
    for (int j = 0; j < 2; j++) {
        int rowB = wn * 32 + j * 16 + r + ((q & 2) ? 8 : 0);
        int colB = (q & 1) ? 4 : 0;
        boff[j] = (uint32_t)(STAGE_A_BYTES + (rowB * PITCH + colB) * 4);
    }

#pragma unroll
    for (int mi = 0; mi < 2; mi++)
#pragma unroll
        for (int nj = 0; nj < 4; nj++)
#pragma unroll
            for (int c = 0; c < 4; c++) acc[mi][nj][c] = 0.0f;

    issue_tile(A, Bt, m0, n0, 0, 0, sb, tid);
    issue_tile(A, Bt, m0, n0, 1, 1, sb, tid);

    for (int kt = 0; kt < KTILES; kt++) {
        if (kt < KTILES - 2) asm volatile("cp.async.wait_group 1;");
        else                 asm volatile("cp.async.wait_group 0;");
        __syncthreads();

        const uint32_t st = sb + (uint32_t)(kt % 3) * STAGE_BYTES;
#pragma unroll
        for (int kk = 0; kk < 8; kk++) {
            uint32_t af[2][4], b01[4], b23[4];
            ldsm4(af[0], st + aoff[0] + kk * 32);
            ldsm4(af[1], st + aoff[1] + kk * 32);
            ldsm4(b01,   st + boff[0] + kk * 32);
            ldsm4(b23,   st + boff[1] + kk * 32);
#pragma unroll
            for (int mi = 0; mi < 2; mi++) {
                mma8(acc[mi][0], af[mi], &b01[0]);
                mma8(acc[mi][1], af[mi], &b01[2]);
                mma8(acc[mi][2], af[mi], &b23[0]);
                mma8(acc[mi][3], af[mi], &b23[2]);
            }
        }
        if (kt + 2 < KTILES)
            issue_tile(A, Bt, m0, n0, kt + 2, (kt + 2) % 3, sb, tid);
    }
}

// ---------------------------------------------------------------------------
// step1: ca1 = relu(drive_t * (1 + sigmoid(ec3 @ wec3ca1)) - ca1bias)
//        writes g_at2 = tf32r(ca1) state; ca1 global only on the last step
// ---------------------------------------------------------------------------
__global__ __launch_bounds__(256) void step1_mma(
    const float* __restrict__ ca1bias,
    float* __restrict__ ca1, float* __restrict__ c1h, int t, int last)
{
    extern __shared__ float sm[];
    float acc[2][4][4];
    gemm_mma_tf32(g_at1, g_wt1, sm, acc);

    const int lane = threadIdx.x & 31, warp = threadIdx.x >> 5;
    const int group = lane >> 2, tig = lane & 3;
    const int wm = warp & 3, wn = warp >> 2;
    const int m0 = blockIdx.y * 128, n0 = blockIdx.x * 64;
    const float* drive = &g_drive[t * NDIM];

#pragma unroll
    for (int mi = 0; mi < 2; mi++)
#pragma unroll
        for (int nj = 0; nj < 4; nj++)
#pragma unroll
            for (int c = 0; c < 4; c++) {
                const int m = m0 + wm * 32 + mi * 16 + group + ((c & 2) ? 8 : 0);
                const int n = n0 + wn * 32 + nj * 8 + tig * 2 + (c & 1);
                float v = fmaxf(drive[n] * (1.0f + sigmoidf(acc[mi][nj][c])) - ca1bias[n], 0.0f);
                const int gi = m * NDIM + n;
                if (last) ca1[gi] = v;
                g_at2[gi] = tf32r(v);
                if (m == 0) c1h[t * NDIM + n] = v;
            }
}

// ---------------------------------------------------------------------------
// step2: ec5 += ca1 @ wca1ec5; squash; ec3 *= ec5; cue @ t==10; threefry noise
//        writes g_at1 = tf32r(ec3) state for the next step1
// ---------------------------------------------------------------------------
__global__ __launch_bounds__(256) void step2_mma(
    const int* __restrict__ cue,
    float* __restrict__ ec3, float* __restrict__ ec5,
    float* __restrict__ e3h, float* __restrict__ e5h, int t)
{
    extern __shared__ float sm[];
    float acc[2][4][4];
    gemm_mma_tf32(g_at2, g_wt2, sm, acc);

    const int lane = threadIdx.x & 31, warp = threadIdx.x >> 5;
    const int group = lane >> 2, tig = lane & 3;
    const int wm = warp & 3, wn = warp >> 2;
    const int m0 = blockIdx.y * 128, n0 = blockIdx.x * 64;
    const uint32_t k0 = g_keys[2 * t], k1 = g_keys[2 * t + 1];
    const bool at_cue = (t == 10);

#pragma unroll
    for (int mi = 0; mi < 2; mi++)
#pragma unroll
        for (int nj = 0; nj < 4; nj++)
#pragma unroll
            for (int c = 0; c < 4; c++) {
                const int m = m0 + wm * 32 + mi * 16 + group + ((c & 2) ? 8 : 0);
                const int n = n0 + wn * 32 + nj * 8 + tig * 2 + (c & 1);
                const int gi = m * NDIM + n;
                float e5 = ec5[gi] + acc[mi][nj][c];       // 10*TS == 1.0 exactly
                e5 = 0.69f + 0.3f * sigmoidf(4.0f * (e5 - 0.3f));
                float e3 = e5 * ec3[gi];
                if (at_cue && (cue[gi] != 0)) e3 = 0.4f * e3 + 0.6f;
                if (noise_hit(k0, k1, (uint32_t)gi)) e3 = 0.5f * e3 + 0.3f;
                ec5[gi] = e5;
                ec3[gi] = e3;
                g_at1[gi] = tf32r(e3);
                if (m == 0) { e5h[t * NDIM + n] = e5; e3h[t * NDIM + n] = e3; }
            }
}

// ---------------------------------------------------------------------------
// act_cell = ca1 @ wca1act + actbias (tf32 operands, validated)
// ---------------------------------------------------------------------------
__global__ __launch_bounds__(128) void act_kernel(
    const float* __restrict__ ca1, const float* __restrict__ w,
    const float* __restrict__ bias, float* __restrict__ out)
{
    __shared__ float s0[128], s1[128];
    const int b = blockIdx.x;
    float a0 = 0.0f, a1 = 0.0f;
    for (int c = threadIdx.x; c < NDIM; c += 128) {
        float v = tf32r(ca1[b * NDIM + c]);
        a0 += v * tf32r(w[c * 2 + 0]);
        a1 += v * tf32r(w[c * 2 + 1]);
    }
    s0[threadIdx.x] = a0; s1[threadIdx.x] = a1;
    __syncthreads();
    for (int off = 64; off > 0; off >>= 1) {
        if (threadIdx.x < off) {
            s0[threadIdx.x] += s0[threadIdx.x + off];
            s1[threadIdx.x] += s1[threadIdx.x + off];
        }
        __syncthreads();
    }
    if (threadIdx.x == 0) {
        out[b * 2 + 0] = s0[0] + bias[0];
        out[b * 2 + 1] = s1[0] + bias[1];
    }
}

// ---------------------------------------------------------------------------
extern "C" void kernel_launch(void* const* d_in, const int* in_sizes, int n_in,
                              void* d_out, int out_size) {
    const int*   cue      = (const int*)d_in[0];     // bool -> int32 in harness
    const float* ec3_last = (const float*)d_in[1];
    const float* ec5_last = (const float*)d_in[2];
    const float* ca1_last = (const float*)d_in[3];
    const float* ca1bias  = (const float*)d_in[4];
    const float* wca3ca1  = (const float*)d_in[5];
    const float* wec3ca1  = (const float*)d_in[6];
    const float* wca1ec5  = (const float*)d_in[7];
    const float* wca1act  = (const float*)d_in[8];
    const float* actbias  = (const float*)d_in[9];

    float* out = (float*)d_out;
    float* act = out + OFF_ACT;
    float* e3h = out + OFF_E3H;
    float* e5h = out + OFF_E5H;
    float* c1h = out + OFF_C1H;
    float* ec3 = out + OFF_EC3;
    float* ec5 = out + OFF_EC5;
    float* ca1 = out + OFF_CA1;

    cudaFuncSetAttribute(step1_mma, cudaFuncAttributeMaxDynamicSharedMemorySize, SMEM_DYN);
    cudaFuncSetAttribute(step2_mma, cudaFuncAttributeMaxDynamicSharedMemorySize, SMEM_DYN);

    cudaMemcpyAsync(ec3, ec3_last, (size_t)BSZ * NDIM * sizeof(float), cudaMemcpyDeviceToDevice);
    cudaMemcpyAsync(ec5, ec5_last, (size_t)BSZ * NDIM * sizeof(float), cudaMemcpyDeviceToDevice);
    cudaMemcpyAsync(ca1, ca1_last, (size_t)BSZ * NDIM * sizeof(float), cudaMemcpyDeviceToDevice);

    keys_kernel<<<1, 128>>>();
    drive_kernel<<<TLEN, 256>>>(wca3ca1);
    transpose_kernel<<<dim3(32, 32), dim3(32, 8)>>>(wec3ca1, 0);
    transpose_kernel<<<dim3(32, 32), dim3(32, 8)>>>(wca1ec5, 1);
    round_init_kernel<<<BSZ * NDIM / 1024, 256>>>(ec3_last);

    dim3 grid(NDIM / 64, BSZ / 128);
    for (int t = 0; t < TLEN; t++) {
        step1_mma<<<grid, 256, SMEM_DYN>>>(ca1bias, ca1, c1h, t, t == TLEN - 1);
        step2_mma<<<grid, 256, SMEM_DYN>>>(cue, ec3, ec5, e3h, e5h, t);
    }
    act_kernel<<<BSZ, 128>>>(ca1, wca1act, actbias, act);
}